// round 8
// baseline (speedup 1.0000x reference)
#include <cuda_runtime.h>
#include <math.h>

#define Bb 256
#define Nn 4096
#define Mm 64
#define Cc 512
#define Hh 4
#define INd 64
#define OUTd 64
#define XK (INd + Hh*Mm)       // 320
#define EPSc 1e-8f

// ---------------- device scratch (accessed ONLY by symbol inside kernels) ----------------
__device__ float g_memS [Bb*Nn*Mm];     // 256MB memory scratch
__device__ float g_x    [Bb*XK];
__device__ float g_gates[Bb*4*Cc];
__device__ float g_c    [Bb*Cc];
__device__ float g_h    [Bb*Cc];
__device__ float g_p    [Bb*560];       // [B][8*70]
__device__ float g_ea   [Bb*512];       // [B][4*128]
__device__ float g_key  [8*Bb*Mm];      // tanh(keys) per head
__device__ float g_scal [8*Bb*8];       // beta,gate,s0,s1,s2,gamma,knorm
__device__ float g_dotA [Bb*Nn];
__device__ float g_dotB [Bb*Nn];
__device__ float g_sumsq[Bb*Nn];
__device__ float g_wA   [Bb*Nn];
__device__ float g_wB   [Bb*Nn];
__device__ float g_reads[4*Bb*Mm];      // reads of heads 0,2,4,6

// ---------------- helpers ----------------
__device__ __forceinline__ float sigm(float x){ return 1.f/(1.f+__expf(-x)); }
__device__ __forceinline__ float softplusf(float x){ return x>20.f? x : log1pf(__expf(x)); }

// ---------------- small kernels ----------------
__global__ void k_build_x(const float* __restrict__ in_data,
                          const float* __restrict__ prev_reads)
{
    int idx = blockIdx.x*blockDim.x + threadIdx.x;
    if (idx >= Bb*XK) return;
    int b = idx / XK, k = idx % XK;
    float v;
    if (k < INd) v = in_data[b*INd + k];
    else {
        int r = (k - INd) >> 6, m = (k - INd) & 63;
        v = prev_reads[(r*Bb + b)*Mm + m];
    }
    g_x[idx] = v;
}

__global__ void k_zero_reads()
{
    int idx = blockIdx.x*blockDim.x + threadIdx.x;
    if (idx < 4*Bb*Mm) g_reads[idx] = 0.f;
}

// ---------------- linear layer; X/C bound to device globals by MODE ----------------
// mode 0: X=g_x  (Kd=320), C=g_gates, store
// mode 1: X=Xarg (h0, Kd=512), C=g_gates, accumulate
// mode 2: X=g_c  (Kd=512), C=g_p,   store
// mode 3: X=g_c  (Kd=512), C=g_ea,  store
__global__ void __launch_bounds__(256) k_lin8(
    const float* __restrict__ Xarg,
    const float* __restrict__ W, const float* __restrict__ bias,
    int Nd, int Kd, int mode)
{
    __shared__ float xs[8][513];
    const float* X = (mode == 0) ? g_x : (mode == 1) ? Xarg : g_c;
    float* C = (mode <= 1) ? g_gates : (mode == 2) ? g_p : g_ea;

    int b0 = blockIdx.y*8;
    int warp = threadIdx.x >> 5, lane = threadIdx.x & 31;
    int j = blockIdx.x*8 + warp;

    for (int t = threadIdx.x; t < 8*Kd; t += 256){
        int bb = t / Kd, k = t - bb*Kd;
        xs[bb][k] = X[(size_t)(b0+bb)*Kd + k];
    }
    __syncthreads();

    if (j < Nd){
        float acc[8];
#pragma unroll
        for (int bb=0;bb<8;bb++) acc[bb]=0.f;
        const float* wr = W + (size_t)j*Kd;
        for (int k = lane; k < Kd; k += 32){
            float w = wr[k];
#pragma unroll
            for (int bb=0;bb<8;bb++) acc[bb] = fmaf(w, xs[bb][k], acc[bb]);
        }
        float bs = bias[j];
#pragma unroll
        for (int bb=0;bb<8;bb++){
            float s = acc[bb];
#pragma unroll
            for (int o=16;o;o>>=1) s += __shfl_xor_sync(0xffffffffu, s, o);
            if (lane == 0){
                size_t oi = (size_t)(b0+bb)*Nd + j;
                if (mode == 1) C[oi] += s + bs;
                else           C[oi]  = s + bs;
            }
        }
    }
}

__global__ void k_lstm(const float* __restrict__ c0)
{
    int idx = blockIdx.x*blockDim.x + threadIdx.x;
    if (idx >= Bb*Cc) return;
    int b = idx >> 9, j = idx & 511;
    const float* g = g_gates + b*(4*Cc);
    float ig = g[j], fg = g[Cc+j], gg = g[2*Cc+j], og = g[3*Cc+j];
    float c = sigm(fg)*c0[idx] + sigm(ig)*tanhf(gg);
    float h = sigm(og)*tanhf(c);
    g_c[idx] = c; g_h[idx] = h;
}

// per-(head,b) parameter transforms; one warp per (hi,b)
__global__ void k_params()
{
    int wg = blockIdx.x*8 + (threadIdx.x>>5);     // 0..2047
    int lane = threadIdx.x & 31;
    int hi = wg >> 8, b = wg & 255;
    const float* pk = g_p + b*560 + hi*70;
    float k0 = tanhf(pk[lane]);
    float k1 = tanhf(pk[lane+32]);
    float* kd = g_key + (hi*Bb + b)*Mm;
    kd[lane] = k0; kd[lane+32] = k1;
    float ss = k0*k0 + k1*k1;
#pragma unroll
    for (int o=16;o;o>>=1) ss += __shfl_xor_sync(0xffffffffu, ss, o);
    if (lane == 0){
        float* sc = g_scal + (hi*Bb + b)*8;
        sc[0] = softplusf(pk[64]);              // beta
        sc[1] = sigm(pk[65]);                   // gate
        float e0 = pk[66], e1 = pk[67], e2 = pk[68];
        float mx = fmaxf(e0, fmaxf(e1,e2));
        float x0 = __expf(e0-mx), x1 = __expf(e1-mx), x2 = __expf(e2-mx);
        float inv = 1.f/(x0+x1+x2);
        sc[2] = x0*inv; sc[3] = x1*inv; sc[4] = x2*inv;
        sc[5] = 1.f + softplusf(pk[69]);        // gamma
        sc[6] = sqrtf(ss);                      // ||k||
    }
}

// ---------------- memory passes ----------------
__global__ void k_passA(const float* __restrict__ src, int hA, int hB)
{
    int b = blockIdx.y;
    int n0 = blockIdx.x*512;
    int lane = threadIdx.x & 31, warp = threadIdx.x >> 5;
    int half = lane >> 4, l16 = lane & 15;
    const float4* ka4 = (const float4*)(g_key + (hA*Bb + b)*Mm);
    const float4* kb4 = (const float4*)(g_key + (hB*Bb + b)*Mm);
    float4 ka = ka4[l16], kb = kb4[l16];
    const float4* s4 = (const float4*)(src) + (size_t)b*Nn*16;
#pragma unroll 2
    for (int it=0; it<32; it++){
        int r = n0 + it*16 + warp*2 + half;
        float4 v = s4[r*16 + l16];
        float da = v.x*ka.x + v.y*ka.y + v.z*ka.z + v.w*ka.w;
        float db = v.x*kb.x + v.y*kb.y + v.z*kb.z + v.w*kb.w;
        float ss = v.x*v.x + v.y*v.y + v.z*v.z + v.w*v.w;
#pragma unroll
        for (int o=8;o;o>>=1){
            da += __shfl_xor_sync(0xffffffffu, da, o);
            db += __shfl_xor_sync(0xffffffffu, db, o);
            ss += __shfl_xor_sync(0xffffffffu, ss, o);
        }
        if (l16 == 0){
            g_dotA [b*Nn + r] = da;
            g_dotB [b*Nn + r] = db;
            g_sumsq[b*Nn + r] = ss;
        }
    }
}

// srcFromArg=1: read from srcArg (harness memory); else read g_memS. dst is always g_memS.
__global__ void k_passB(const float* __restrict__ srcArg, int srcFromArg,
                        int hh, int hA2, int hB2, int readIdx)
{
    __shared__ float sread[64];
    int b = blockIdx.y;
    int n0 = blockIdx.x*512;
    int tid = threadIdx.x;
    int lane = tid & 31, warp = tid >> 5;
    int half = lane >> 4, l16 = lane & 15;
    if (tid < 64) sread[tid] = 0.f;
    __syncthreads();

    const float4* ka4 = (const float4*)(g_key + (hA2*Bb + b)*Mm);
    const float4* kb4 = (const float4*)(g_key + (hB2*Bb + b)*Mm);
    float4 ka = ka4[l16], kb = kb4[l16];
    const float* eap = g_ea + b*512 + hh*128;
    float ex[4], ax[4];
#pragma unroll
    for (int q=0;q<4;q++){
        ex[q] = sigm(eap[l16*4+q]);
        ax[q] = tanhf(eap[64 + l16*4+q]);
    }
    const float* srcp = srcFromArg ? srcArg : (const float*)g_memS;
    const float4* s4 = (const float4*)(srcp) + (size_t)b*Nn*16;
    float4* d4 = (float4*)(g_memS) + (size_t)b*Nn*16;
    const float* wR = g_wA + b*Nn;
    const float* wW = g_wB + b*Nn;
    float4 racc = make_float4(0.f,0.f,0.f,0.f);
#pragma unroll 2
    for (int it=0; it<32; it++){
        int r = n0 + it*16 + warp*2 + half;
        float wr = __ldg(&wR[r]);
        float ww = __ldg(&wW[r]);
        float4 v = s4[r*16 + l16];
        racc.x = fmaf(wr, v.x, racc.x);
        racc.y = fmaf(wr, v.y, racc.y);
        racc.z = fmaf(wr, v.z, racc.z);
        racc.w = fmaf(wr, v.w, racc.w);
        float4 nv;
        nv.x = fmaf(v.x, 1.f - ww*ex[0], ww*ax[0]);
        nv.y = fmaf(v.y, 1.f - ww*ex[1], ww*ax[1]);
        nv.z = fmaf(v.z, 1.f - ww*ex[2], ww*ax[2]);
        nv.w = fmaf(v.w, 1.f - ww*ex[3], ww*ax[3]);
        d4[r*16 + l16] = nv;
        float da = nv.x*ka.x + nv.y*ka.y + nv.z*ka.z + nv.w*ka.w;
        float db = nv.x*kb.x + nv.y*kb.y + nv.z*kb.z + nv.w*kb.w;
        float ss = nv.x*nv.x + nv.y*nv.y + nv.z*nv.z + nv.w*nv.w;
#pragma unroll
        for (int o=8;o;o>>=1){
            da += __shfl_xor_sync(0xffffffffu, da, o);
            db += __shfl_xor_sync(0xffffffffu, db, o);
            ss += __shfl_xor_sync(0xffffffffu, ss, o);
        }
        if (l16 == 0){
            g_dotA [b*Nn + r] = da;
            g_dotB [b*Nn + r] = db;
            g_sumsq[b*Nn + r] = ss;
        }
    }
    racc.x += __shfl_xor_sync(0xffffffffu, racc.x, 16);
    racc.y += __shfl_xor_sync(0xffffffffu, racc.y, 16);
    racc.z += __shfl_xor_sync(0xffffffffu, racc.z, 16);
    racc.w += __shfl_xor_sync(0xffffffffu, racc.w, 16);
    if (lane < 16){
        atomicAdd(&sread[lane*4+0], racc.x);
        atomicAdd(&sread[lane*4+1], racc.y);
        atomicAdd(&sread[lane*4+2], racc.z);
        atomicAdd(&sread[lane*4+3], racc.w);
    }
    __syncthreads();
    if (tid < 64) atomicAdd(&g_reads[(readIdx*Bb + b)*Mm + tid], sread[tid]);
}

// final read-only pass over g_memS
__global__ void k_passC(int readIdx)
{
    __shared__ float sread[64];
    int b = blockIdx.y;
    int n0 = blockIdx.x*512;
    int tid = threadIdx.x;
    int lane = tid & 31, warp = tid >> 5;
    int half = lane >> 4, l16 = lane & 15;
    if (tid < 64) sread[tid] = 0.f;
    __syncthreads();
    const float4* s4 = (const float4*)(g_memS) + (size_t)b*Nn*16;
    const float* wR = g_wA + b*Nn;
    float4 racc = make_float4(0.f,0.f,0.f,0.f);
#pragma unroll 2
    for (int it=0; it<32; it++){
        int r = n0 + it*16 + warp*2 + half;
        float wr = __ldg(&wR[r]);
        float4 v = s4[r*16 + l16];
        racc.x = fmaf(wr, v.x, racc.x);
        racc.y = fmaf(wr, v.y, racc.y);
        racc.z = fmaf(wr, v.z, racc.z);
        racc.w = fmaf(wr, v.w, racc.w);
    }
    racc.x += __shfl_xor_sync(0xffffffffu, racc.x, 16);
    racc.y += __shfl_xor_sync(0xffffffffu, racc.y, 16);
    racc.z += __shfl_xor_sync(0xffffffffu, racc.z, 16);
    racc.w += __shfl_xor_sync(0xffffffffu, racc.w, 16);
    if (lane < 16){
        atomicAdd(&sread[lane*4+0], racc.x);
        atomicAdd(&sread[lane*4+1], racc.y);
        atomicAdd(&sread[lane*4+2], racc.z);
        atomicAdd(&sread[lane*4+3], racc.w);
    }
    __syncthreads();
    if (tid < 64) atomicAdd(&g_reads[(readIdx*Bb + b)*Mm + tid], sread[tid]);
}

// ---------------- weight computation ----------------
__device__ __forceinline__ float blockMax(float v, float* red)
{
#pragma unroll
    for (int o=16;o;o>>=1) v = fmaxf(v, __shfl_xor_sync(0xffffffffu, v, o));
    int w = threadIdx.x >> 5;
    if ((threadIdx.x & 31) == 0) red[w] = v;
    __syncthreads();
    if (threadIdx.x < 32){
        float x = (threadIdx.x < 16) ? red[threadIdx.x] : -INFINITY;
#pragma unroll
        for (int o=8;o;o>>=1) x = fmaxf(x, __shfl_xor_sync(0xffffffffu, x, o));
        if (threadIdx.x == 0) red[0] = x;
    }
    __syncthreads();
    float r = red[0];
    __syncthreads();
    return r;
}

__device__ __forceinline__ float blockSum(float v, float* red)
{
#pragma unroll
    for (int o=16;o;o>>=1) v += __shfl_xor_sync(0xffffffffu, v, o);
    int w = threadIdx.x >> 5;
    if ((threadIdx.x & 31) == 0) red[w] = v;
    __syncthreads();
    if (threadIdx.x < 32){
        float x = (threadIdx.x < 16) ? red[threadIdx.x] : 0.f;
#pragma unroll
        for (int o=8;o;o>>=1) x += __shfl_xor_sync(0xffffffffu, x, o);
        if (threadIdx.x == 0) red[0] = x;
    }
    __syncthreads();
    float r = red[0];
    __syncthreads();
    return r;
}

__global__ void __launch_bounds__(512) k_wpair(int hA, int hB, const float* __restrict__ prevW)
{
    __shared__ float nm_s[Nn];
    __shared__ float wg_s[Nn];
    __shared__ float red[32];
    int b = blockIdx.x;
    int tid = threadIdx.x;

    for (int n = tid; n < Nn; n += 512)
        nm_s[n] = sqrtf(g_sumsq[b*Nn + n]);
    __syncthreads();

    for (int pass = 0; pass < 2; pass++){
        int hi = pass ? hB : hA;
        const float* dot  = pass ? g_dotB : g_dotA;
        float*       wout = pass ? g_wB   : g_wA;
        const float* sc = g_scal + (hi*Bb + b)*8;
        float beta = sc[0], gate = sc[1];
        float s0 = sc[2], s1 = sc[3], s2 = sc[4];
        float gamma = sc[5], kn = sc[6];

        float v[8]; float lmax = -INFINITY;
#pragma unroll
        for (int i=0;i<8;i++){
            int n = tid + i*512;
            float d = dot[b*Nn + n];
            float s = beta * d / (nm_s[n]*kn + EPSc);
            v[i] = s; lmax = fmaxf(lmax, s);
        }
        float mx = blockMax(lmax, red);
        float lsum = 0.f;
#pragma unroll
        for (int i=0;i<8;i++){ v[i] = __expf(v[i]-mx); lsum += v[i]; }
        float inv = 1.f / blockSum(lsum, red);
        const float* pw = prevW + ((size_t)hi*Bb + b)*Nn;
#pragma unroll
        for (int i=0;i<8;i++){
            int n = tid + i*512;
            float wc = v[i]*inv;
            wg_s[n] = gate*wc + (1.f-gate)*pw[n];
        }
        __syncthreads();
        float wp[8]; float lsum2 = 0.f;
#pragma unroll
        for (int i=0;i<8;i++){
            int n = tid + i*512;
            float ws = s0*wg_s[(n+Nn-1)&(Nn-1)] + s1*wg_s[n] + s2*wg_s[(n+1)&(Nn-1)];
            float p = powf(ws, gamma);
            wp[i] = p; lsum2 += p;
        }
        float inv2 = 1.f / (blockSum(lsum2, red) + EPSc);
#pragma unroll
        for (int i=0;i<8;i++){
            int n = tid + i*512;
            wout[b*Nn + n] = wp[i]*inv2;
        }
        __syncthreads();
    }
}

// ---------------- output ----------------
__global__ void k_out(const float* __restrict__ W_out, const float* __restrict__ b_out,
                      float* __restrict__ out)
{
    int wg = blockIdx.x*8 + (threadIdx.x>>5);      // 0..16383
    int lane = threadIdx.x & 31;
    int b = wg >> 6, j = wg & 63;
    float acc = 0.f;
    for (int k = lane; k < Cc + Hh*Mm; k += 32){
        float s;
        if (k < Cc) s = g_h[b*Cc + k];
        else {
            int kk = k - Cc;
            s = g_reads[((kk>>6)*Bb + b)*Mm + (kk & 63)];
        }
        acc = fmaf(s, W_out[j*(Cc+Hh*Mm) + k], acc);
    }
#pragma unroll
    for (int o=16;o;o>>=1) acc += __shfl_xor_sync(0xffffffffu, acc, o);
    if (lane == 0) out[b*OUTd + j] = 1.f/(1.f + __expf(-(acc + b_out[j])));
}

// ---------------- launch ----------------
extern "C" void kernel_launch(void* const* d_in, const int* in_sizes, int n_in,
                              void* d_out, int out_size)
{
    // Resolve inputs BY ELEMENT COUNT (robust to any input ordering).
    const float *in_data=0, *memory=0, *h0=0, *c0=0, *prevW=0, *prevR=0;
    const float *W_ih=0, *b_ih=0, *W_hh=0, *b_hh=0, *W_out=0, *b_out=0;
    const float *W_addr=0, *b_addr=0, *W_ea=0, *b_ea=0;
    for (int i = 0; i < n_in; i++){
        const float* p = (const float*)d_in[i];
        switch (in_sizes[i]){
            case 16384:    in_data = p; break;
            case 67108864: memory  = p; break;
            case 131072:   if (!h0) h0 = p; else c0 = p; break;
            case 8388608:  prevW   = p; break;
            case 65536:    prevR   = p; break;
            case 655360:   W_ih    = p; break;
            case 2048:     if (!b_ih) b_ih = p; else b_hh = p; break;
            case 1048576:  W_hh    = p; break;
            case 49152:    W_out   = p; break;
            case 64:       b_out   = p; break;
            case 286720:   W_addr  = p; break;
            case 560:      b_addr  = p; break;
            case 262144:   W_ea    = p; break;
            case 512:      b_ea    = p; break;
            default: break;
        }
    }
    float* out = (float*)d_out;

    // controller: gates = x@W_ih.T + b_ih + h0@W_hh.T + b_hh
    k_build_x<<<(Bb*XK+255)/256, 256>>>(in_data, prevR);
    k_lin8<<<dim3(4*Cc/8, Bb/8), 256>>>(0,  W_ih, b_ih, 4*Cc, XK, 0);
    k_lin8<<<dim3(4*Cc/8, Bb/8), 256>>>(h0, W_hh, b_hh, 4*Cc, Cc, 1);
    k_lstm<<<(Bb*Cc+255)/256, 256>>>(c0);

    // head params: p = c@W_addr.T + b_addr ; ea = c@W_ea.T + b_ea
    k_lin8<<<dim3(70, Bb/8), 256>>>(0, W_addr, b_addr, 560, Cc, 2);
    k_lin8<<<dim3(64, Bb/8), 256>>>(0, W_ea,  b_ea,  512, Cc, 3);
    k_params<<<256, 256>>>();
    k_zero_reads<<<(4*Bb*Mm+255)/256, 256>>>();

    // fused memory passes
    dim3 pg(Nn/512, Bb);
    k_passA<<<pg, 256>>>(memory, 0, 1);
    k_wpair<<<Bb, 512>>>(0, 1, prevW);
    k_passB<<<pg, 256>>>(memory, 1, /*ea*/0, /*next keys*/2, 3, /*read*/0);
    k_wpair<<<Bb, 512>>>(2, 3, prevW);
    k_passB<<<pg, 256>>>(0, 0, 1, 4, 5, 1);
    k_wpair<<<Bb, 512>>>(4, 5, prevW);
    k_passB<<<pg, 256>>>(0, 0, 2, 6, 7, 2);
    k_wpair<<<Bb, 512>>>(6, 7, prevW);          // head 7's write is dead; w7 unused
    k_passC<<<pg, 256>>>(3);

    // output
    k_out<<<(Bb*OUTd)/8, 256>>>(W_out, b_out, out);
}

// round 12
// speedup vs baseline: 1.2093x; 1.2093x over previous
#include <cuda_runtime.h>
#include <cuda_fp16.h>
#include <math.h>

#define Bb 256
#define Nn 4096
#define Mm 64
#define Cc 512
#define Hh 4
#define INd 64
#define OUTd 64
#define XK (INd + Hh*Mm)       // 320
#define GK (XK + Cc)           // 832 (concat K for gates)
#define EPSc 1e-8f

// ---------------- device scratch (accessed ONLY by symbol inside kernels) ----------------
__device__ __half g_memH[Bb*Nn*Mm];     // 128MB fp16 memory scratch
__device__ float g_x    [Bb*XK];
__device__ float g_gates[Bb*4*Cc];
__device__ float g_c    [Bb*Cc];
__device__ float g_h    [Bb*Cc];
__device__ float g_p    [Bb*560];       // [B][8*70]
__device__ float g_ea   [Bb*512];       // [B][4*128]
__device__ float g_key  [8*Bb*Mm];      // tanh(keys) per head
__device__ float g_scal [8*Bb*8];       // beta,gate,s0,s1,s2,gamma,knorm
__device__ float g_dotA [Bb*Nn];
__device__ float g_dotB [Bb*Nn];
__device__ float g_sumsq[Bb*Nn];
__device__ float g_wA   [Bb*Nn];
__device__ float g_wB   [Bb*Nn];
__device__ float g_reads[4*Bb*Mm];      // reads of heads 0,2,4,6

// ---------------- helpers ----------------
__device__ __forceinline__ float sigm(float x){ return 1.f/(1.f+__expf(-x)); }
__device__ __forceinline__ float softplusf(float x){ return x>20.f? x : log1pf(__expf(x)); }

// ---------------- prep: build x and zero reads ----------------
__global__ void k_prep(const float* __restrict__ in_data,
                       const float* __restrict__ prev_reads)
{
    int idx = blockIdx.x*blockDim.x + threadIdx.x;
    if (idx < Bb*XK){
        int b = idx / XK, k = idx % XK;
        float v;
        if (k < INd) v = in_data[b*INd + k];
        else {
            int r = (k - INd) >> 6, m = (k - INd) & 63;
            v = prev_reads[(r*Bb + b)*Mm + m];
        }
        g_x[idx] = v;
    }
    if (idx < 4*Bb*Mm) g_reads[idx] = 0.f;
}

// ---------------- fused gates: g_gates[b,j] = x@W_ih.T + h0@W_hh.T + b_ih + b_hh ----------------
__global__ void __launch_bounds__(256) k_gates(
    const float* __restrict__ h0,
    const float* __restrict__ W_ih, const float* __restrict__ b_ih,
    const float* __restrict__ W_hh, const float* __restrict__ b_hh)
{
    __shared__ float xs[8][GK+1];
    int b0 = blockIdx.y*8;
    int warp = threadIdx.x >> 5, lane = threadIdx.x & 31;
    int j = blockIdx.x*8 + warp;

    for (int t = threadIdx.x; t < 8*GK; t += 256){
        int bb = t / GK, k = t - bb*GK;
        xs[bb][k] = (k < XK) ? g_x[(size_t)(b0+bb)*XK + k]
                             : h0[(size_t)(b0+bb)*Cc + (k - XK)];
    }
    __syncthreads();

    float acc[8];
#pragma unroll
    for (int bb=0;bb<8;bb++) acc[bb]=0.f;
    const float* w1 = W_ih + (size_t)j*XK;
    for (int k = lane; k < XK; k += 32){
        float w = w1[k];
#pragma unroll
        for (int bb=0;bb<8;bb++) acc[bb] = fmaf(w, xs[bb][k], acc[bb]);
    }
    const float* w2 = W_hh + (size_t)j*Cc;
    for (int k = lane; k < Cc; k += 32){
        float w = w2[k];
#pragma unroll
        for (int bb=0;bb<8;bb++) acc[bb] = fmaf(w, xs[bb][XK+k], acc[bb]);
    }
    float bs = b_ih[j] + b_hh[j];
#pragma unroll
    for (int bb=0;bb<8;bb++){
        float s = acc[bb];
#pragma unroll
        for (int o=16;o;o>>=1) s += __shfl_xor_sync(0xffffffffu, s, o);
        if (lane == 0) g_gates[(size_t)(b0+bb)*(4*Cc) + j] = s + bs;
    }
}

__global__ void k_lstm(const float* __restrict__ c0)
{
    int idx = blockIdx.x*blockDim.x + threadIdx.x;
    if (idx >= Bb*Cc) return;
    int b = idx >> 9, j = idx & 511;
    const float* g = g_gates + b*(4*Cc);
    float ig = g[j], fg = g[Cc+j], gg = g[2*Cc+j], og = g[3*Cc+j];
    float c = sigm(fg)*c0[idx] + sigm(ig)*tanhf(gg);
    float h = sigm(og)*tanhf(c);
    g_c[idx] = c; g_h[idx] = h;
}

// ---------------- fused addr+ea projections from g_c ----------------
__global__ void __launch_bounds__(256) k_addrea(
    const float* __restrict__ W_addr, const float* __restrict__ b_addr,
    const float* __restrict__ W_ea,  const float* __restrict__ b_ea)
{
    __shared__ float xs[8][Cc+1];
    int b0 = blockIdx.y*8;
    int warp = threadIdx.x >> 5, lane = threadIdx.x & 31;
    int j = blockIdx.x*8 + warp;       // 0..1071

    for (int t = threadIdx.x; t < 8*Cc; t += 256){
        int bb = t >> 9, k = t & 511;
        xs[bb][k] = g_c[(size_t)(b0+bb)*Cc + k];
    }
    __syncthreads();

    const float* wr; float bs; float* C; int Nd; int jj;
    if (j < 560){ jj = j;      wr = W_addr + (size_t)jj*Cc; bs = b_addr[jj]; C = g_p;  Nd = 560; }
    else        { jj = j-560;  wr = W_ea  + (size_t)jj*Cc;  bs = b_ea[jj];  C = g_ea; Nd = 512; }

    float acc[8];
#pragma unroll
    for (int bb=0;bb<8;bb++) acc[bb]=0.f;
    for (int k = lane; k < Cc; k += 32){
        float w = wr[k];
#pragma unroll
        for (int bb=0;bb<8;bb++) acc[bb] = fmaf(w, xs[bb][k], acc[bb]);
    }
#pragma unroll
    for (int bb=0;bb<8;bb++){
        float s = acc[bb];
#pragma unroll
        for (int o=16;o;o>>=1) s += __shfl_xor_sync(0xffffffffu, s, o);
        if (lane == 0) C[(size_t)(b0+bb)*Nd + jj] = s + bs;
    }
}

// per-(head,b) parameter transforms; one warp per (hi,b)
__global__ void k_params()
{
    int wg = blockIdx.x*8 + (threadIdx.x>>5);     // 0..2047
    int lane = threadIdx.x & 31;
    int hi = wg >> 8, b = wg & 255;
    const float* pk = g_p + b*560 + hi*70;
    float k0 = tanhf(pk[lane]);
    float k1 = tanhf(pk[lane+32]);
    float* kd = g_key + (hi*Bb + b)*Mm;
    kd[lane] = k0; kd[lane+32] = k1;
    float ss = k0*k0 + k1*k1;
#pragma unroll
    for (int o=16;o;o>>=1) ss += __shfl_xor_sync(0xffffffffu, ss, o);
    if (lane == 0){
        float* sc = g_scal + (hi*Bb + b)*8;
        sc[0] = softplusf(pk[64]);              // beta
        sc[1] = sigm(pk[65]);                   // gate
        float e0 = pk[66], e1 = pk[67], e2 = pk[68];
        float mx = fmaxf(e0, fmaxf(e1,e2));
        float x0 = __expf(e0-mx), x1 = __expf(e1-mx), x2 = __expf(e2-mx);
        float inv = 1.f/(x0+x1+x2);
        sc[2] = x0*inv; sc[3] = x1*inv; sc[4] = x2*inv;
        sc[5] = 1.f + softplusf(pk[69]);        // gamma
        sc[6] = sqrtf(ss);                      // ||k||
    }
}

// ---------------- memory passes ----------------
// P1: dots + sumsq over fp32 harness memory
__global__ void k_passA(const float* __restrict__ src, int hA, int hB)
{
    int b = blockIdx.y;
    int n0 = blockIdx.x*512;
    int lane = threadIdx.x & 31, warp = threadIdx.x >> 5;
    int half = lane >> 4, l16 = lane & 15;
    const float4* ka4 = (const float4*)(g_key + (hA*Bb + b)*Mm);
    const float4* kb4 = (const float4*)(g_key + (hB*Bb + b)*Mm);
    float4 ka = ka4[l16], kb = kb4[l16];
    const float4* s4 = (const float4*)(src) + (size_t)b*Nn*16;
#pragma unroll 2
    for (int it=0; it<32; it++){
        int r = n0 + it*16 + warp*2 + half;
        float4 v = s4[r*16 + l16];
        float da = v.x*ka.x + v.y*ka.y + v.z*ka.z + v.w*ka.w;
        float db = v.x*kb.x + v.y*kb.y + v.z*kb.z + v.w*kb.w;
        float ss = v.x*v.x + v.y*v.y + v.z*v.z + v.w*v.w;
#pragma unroll
        for (int o=8;o;o>>=1){
            da += __shfl_xor_sync(0xffffffffu, da, o);
            db += __shfl_xor_sync(0xffffffffu, db, o);
            ss += __shfl_xor_sync(0xffffffffu, ss, o);
        }
        if (l16 == 0){
            g_dotA [b*Nn + r] = da;
            g_dotB [b*Nn + r] = db;
            g_sumsq[b*Nn + r] = ss;
        }
    }
}

__device__ __forceinline__ float4 h4_to_f4(uint2 u){
    float2 f0 = __half22float2(*(__half2*)&u.x);
    float2 f1 = __half22float2(*(__half2*)&u.y);
    return make_float4(f0.x, f0.y, f1.x, f1.y);
}
__device__ __forceinline__ uint2 f4_to_h4(float4 v){
    __half2 a0 = __floats2half2_rn(v.x, v.y);
    __half2 a1 = __floats2half2_rn(v.z, v.w);
    uint2 o; o.x = *(unsigned*)&a0; o.y = *(unsigned*)&a1; return o;
}

// first write pass: fp32 src (harness memory) -> half g_memH, + read-acc + next dots
__global__ void k_passB1(const float* __restrict__ srcArg,
                         int hh, int hA2, int hB2, int readIdx)
{
    __shared__ float sread[64];
    int b = blockIdx.y;
    int n0 = blockIdx.x*512;
    int tid = threadIdx.x;
    int lane = tid & 31, warp = tid >> 5;
    int half = lane >> 4, l16 = lane & 15;
    if (tid < 64) sread[tid] = 0.f;
    __syncthreads();

    const float4* ka4 = (const float4*)(g_key + (hA2*Bb + b)*Mm);
    const float4* kb4 = (const float4*)(g_key + (hB2*Bb + b)*Mm);
    float4 ka = ka4[l16], kb = kb4[l16];
    const float* eap = g_ea + b*512 + hh*128;
    float ex[4], ax[4];
#pragma unroll
    for (int q=0;q<4;q++){
        ex[q] = sigm(eap[l16*4+q]);
        ax[q] = tanhf(eap[64 + l16*4+q]);
    }
    const float4* s4 = (const float4*)(srcArg) + (size_t)b*Nn*16;
    uint2* d2 = (uint2*)(g_memH) + (size_t)b*Nn*16;
    const float* wR = g_wA + b*Nn;
    const float* wW = g_wB + b*Nn;
    float4 racc = make_float4(0.f,0.f,0.f,0.f);
#pragma unroll 2
    for (int it=0; it<32; it++){
        int r = n0 + it*16 + warp*2 + half;
        float wr = __ldg(&wR[r]);
        float ww = __ldg(&wW[r]);
        float4 v = s4[r*16 + l16];
        racc.x = fmaf(wr, v.x, racc.x);
        racc.y = fmaf(wr, v.y, racc.y);
        racc.z = fmaf(wr, v.z, racc.z);
        racc.w = fmaf(wr, v.w, racc.w);
        float4 nv;
        nv.x = fmaf(v.x, 1.f - ww*ex[0], ww*ax[0]);
        nv.y = fmaf(v.y, 1.f - ww*ex[1], ww*ax[1]);
        nv.z = fmaf(v.z, 1.f - ww*ex[2], ww*ax[2]);
        nv.w = fmaf(v.w, 1.f - ww*ex[3], ww*ax[3]);
        d2[r*16 + l16] = f4_to_h4(nv);
        float da = nv.x*ka.x + nv.y*ka.y + nv.z*ka.z + nv.w*ka.w;
        float db = nv.x*kb.x + nv.y*kb.y + nv.z*kb.z + nv.w*kb.w;
        float ss = nv.x*nv.x + nv.y*nv.y + nv.z*nv.z + nv.w*nv.w;
#pragma unroll
        for (int o=8;o;o>>=1){
            da += __shfl_xor_sync(0xffffffffu, da, o);
            db += __shfl_xor_sync(0xffffffffu, db, o);
            ss += __shfl_xor_sync(0xffffffffu, ss, o);
        }
        if (l16 == 0){
            g_dotA [b*Nn + r] = da;
            g_dotB [b*Nn + r] = db;
            g_sumsq[b*Nn + r] = ss;
        }
    }
    racc.x += __shfl_xor_sync(0xffffffffu, racc.x, 16);
    racc.y += __shfl_xor_sync(0xffffffffu, racc.y, 16);
    racc.z += __shfl_xor_sync(0xffffffffu, racc.z, 16);
    racc.w += __shfl_xor_sync(0xffffffffu, racc.w, 16);
    if (lane < 16){
        atomicAdd(&sread[lane*4+0], racc.x);
        atomicAdd(&sread[lane*4+1], racc.y);
        atomicAdd(&sread[lane*4+2], racc.z);
        atomicAdd(&sread[lane*4+3], racc.w);
    }
    __syncthreads();
    if (tid < 64) atomicAdd(&g_reads[(readIdx*Bb + b)*Mm + tid], sread[tid]);
}

// in-place half pass: g_memH -> g_memH
__global__ void k_passBH(int hh, int hA2, int hB2, int readIdx)
{
    __shared__ float sread[64];
    int b = blockIdx.y;
    int n0 = blockIdx.x*512;
    int tid = threadIdx.x;
    int lane = tid & 31, warp = tid >> 5;
    int half = lane >> 4, l16 = lane & 15;
    if (tid < 64) sread[tid] = 0.f;
    __syncthreads();

    const float4* ka4 = (const float4*)(g_key + (hA2*Bb + b)*Mm);
    const float4* kb4 = (const float4*)(g_key + (hB2*Bb + b)*Mm);
    float4 ka = ka4[l16], kb = kb4[l16];
    const float* eap = g_ea + b*512 + hh*128;
    float ex[4], ax[4];
#pragma unroll
    for (int q=0;q<4;q++){
        ex[q] = sigm(eap[l16*4+q]);
        ax[q] = tanhf(eap[64 + l16*4+q]);
    }
    uint2* m2 = (uint2*)(g_memH) + (size_t)b*Nn*16;
    const float* wR = g_wA + b*Nn;
    const float* wW = g_wB + b*Nn;
    float4 racc = make_float4(0.f,0.f,0.f,0.f);
#pragma unroll 2
    for (int it=0; it<32; it++){
        int r = n0 + it*16 + warp*2 + half;
        float wr = __ldg(&wR[r]);
        float ww = __ldg(&wW[r]);
        float4 v = h4_to_f4(m2[r*16 + l16]);
        racc.x = fmaf(wr, v.x, racc.x);
        racc.y = fmaf(wr, v.y, racc.y);
        racc.z = fmaf(wr, v.z, racc.z);
        racc.w = fmaf(wr, v.w, racc.w);
        float4 nv;
        nv.x = fmaf(v.x, 1.f - ww*ex[0], ww*ax[0]);
        nv.y = fmaf(v.y, 1.f - ww*ex[1], ww*ax[1]);
        nv.z = fmaf(v.z, 1.f - ww*ex[2], ww*ax[2]);
        nv.w = fmaf(v.w, 1.f - ww*ex[3], ww*ax[3]);
        m2[r*16 + l16] = f4_to_h4(nv);
        float da = nv.x*ka.x + nv.y*ka.y + nv.z*ka.z + nv.w*ka.w;
        float db = nv.x*kb.x + nv.y*kb.y + nv.z*kb.z + nv.w*kb.w;
        float ss = nv.x*nv.x + nv.y*nv.y + nv.z*nv.z + nv.w*nv.w;
#pragma unroll
        for (int o=8;o;o>>=1){
            da += __shfl_xor_sync(0xffffffffu, da, o);
            db += __shfl_xor_sync(0xffffffffu, db, o);
            ss += __shfl_xor_sync(0xffffffffu, ss, o);
        }
        if (l16 == 0){
            g_dotA [b*Nn + r] = da;
            g_dotB [b*Nn + r] = db;
            g_sumsq[b*Nn + r] = ss;
        }
    }
    racc.x += __shfl_xor_sync(0xffffffffu, racc.x, 16);
    racc.y += __shfl_xor_sync(0xffffffffu, racc.y, 16);
    racc.z += __shfl_xor_sync(0xffffffffu, racc.z, 16);
    racc.w += __shfl_xor_sync(0xffffffffu, racc.w, 16);
    if (lane < 16){
        atomicAdd(&sread[lane*4+0], racc.x);
        atomicAdd(&sread[lane*4+1], racc.y);
        atomicAdd(&sread[lane*4+2], racc.z);
        atomicAdd(&sread[lane*4+3], racc.w);
    }
    __syncthreads();
    if (tid < 64) atomicAdd(&g_reads[(readIdx*Bb + b)*Mm + tid], sread[tid]);
}

// final read-only pass over half g_memH
__global__ void k_passC(int readIdx)
{
    __shared__ float sread[64];
    int b = blockIdx.y;
    int n0 = blockIdx.x*512;
    int tid = threadIdx.x;
    int lane = tid & 31, warp = tid >> 5;
    int half = lane >> 4, l16 = lane & 15;
    if (tid < 64) sread[tid] = 0.f;
    __syncthreads();
    const uint2* m2 = (const uint2*)(g_memH) + (size_t)b*Nn*16;
    const float* wR = g_wA + b*Nn;
    float4 racc = make_float4(0.f,0.f,0.f,0.f);
#pragma unroll 2
    for (int it=0; it<32; it++){
        int r = n0 + it*16 + warp*2 + half;
        float wr = __ldg(&wR[r]);
        float4 v = h4_to_f4(m2[r*16 + l16]);
        racc.x = fmaf(wr, v.x, racc.x);
        racc.y = fmaf(wr, v.y, racc.y);
        racc.z = fmaf(wr, v.z, racc.z);
        racc.w = fmaf(wr, v.w, racc.w);
    }
    racc.x += __shfl_xor_sync(0xffffffffu, racc.x, 16);
    racc.y += __shfl_xor_sync(0xffffffffu, racc.y, 16);
    racc.z += __shfl_xor_sync(0xffffffffu, racc.z, 16);
    racc.w += __shfl_xor_sync(0xffffffffu, racc.w, 16);
    if (lane < 16){
        atomicAdd(&sread[lane*4+0], racc.x);
        atomicAdd(&sread[lane*4+1], racc.y);
        atomicAdd(&sread[lane*4+2], racc.z);
        atomicAdd(&sread[lane*4+3], racc.w);
    }
    __syncthreads();
    if (tid < 64) atomicAdd(&g_reads[(readIdx*Bb + b)*Mm + tid], sread[tid]);
}

// ---------------- weight computation ----------------
__device__ __forceinline__ float blockMax(float v, float* red)
{
#pragma unroll
    for (int o=16;o;o>>=1) v = fmaxf(v, __shfl_xor_sync(0xffffffffu, v, o));
    int w = threadIdx.x >> 5;
    if ((threadIdx.x & 31) == 0) red[w] = v;
    __syncthreads();
    if (threadIdx.x < 32){
        float x = (threadIdx.x < 16) ? red[threadIdx.x] : -INFINITY;
#pragma unroll
        for (int o=8;o;o>>=1) x = fmaxf(x, __shfl_xor_sync(0xffffffffu, x, o));
        if (threadIdx.x == 0) red[0] = x;
    }
    __syncthreads();
    float r = red[0];
    __syncthreads();
    return r;
}

__device__ __forceinline__ float blockSum(float v, float* red)
{
#pragma unroll
    for (int o=16;o;o>>=1) v += __shfl_xor_sync(0xffffffffu, v, o);
    int w = threadIdx.x >> 5;
    if ((threadIdx.x & 31) == 0) red[w] = v;
    __syncthreads();
    if (threadIdx.x < 32){
        float x = (threadIdx.x < 16) ? red[threadIdx.x] : 0.f;
#pragma unroll
        for (int o=8;o;o>>=1) x += __shfl_xor_sync(0xffffffffu, x, o);
        if (threadIdx.x == 0) red[0] = x;
    }
    __syncthreads();
    float r = red[0];
    __syncthreads();
    return r;
}

__global__ void __launch_bounds__(512) k_wpair(int hA, int hB, const float* __restrict__ prevW)
{
    __shared__ float nm_s[Nn];
    __shared__ float wg_s[Nn];
    __shared__ float red[32];
    int b = blockIdx.x;
    int tid = threadIdx.x;

    for (int n = tid; n < Nn; n += 512)
        nm_s[n] = sqrtf(g_sumsq[b*Nn + n]);
    __syncthreads();

    for (int pass = 0; pass < 2; pass++){
        int hi = pass ? hB : hA;
        const float* dot  = pass ? g_dotB : g_dotA;
        float*       wout = pass ? g_wB   : g_wA;
        const float* sc = g_scal + (hi*Bb + b)*8;
        float beta = sc[0], gate = sc[1];
        float s0 = sc[2], s1 = sc[3], s2 = sc[4];
        float gamma = sc[5], kn = sc[6];

        float v[8]; float lmax = -INFINITY;
#pragma unroll
        for (int i=0;i<8;i++){
            int n = tid + i*512;
            float d = dot[b*Nn + n];
            float s = beta * d / (nm_s[n]*kn + EPSc);
            v[i] = s; lmax = fmaxf(lmax, s);
        }
        float mx = blockMax(lmax, red);
        float lsum = 0.f;
#pragma unroll
        for (int i=0;i<8;i++){ v[i] = __expf(v[i]-mx); lsum += v[i]; }
        float inv = 1.f / blockSum(lsum, red);
        const float* pw = prevW + ((size_t)hi*Bb + b)*Nn;
#pragma unroll
        for (int i=0;i<8;i++){
            int n = tid + i*512;
            float wc = v[i]*inv;
            wg_s[n] = gate*wc + (1.f-gate)*pw[n];
        }
        __syncthreads();
        float wp[8]; float lsum2 = 0.f;
#pragma unroll
        for (int i=0;i<8;i++){
            int n = tid + i*512;
            float ws = s0*wg_s[(n+Nn-1)&(Nn-1)] + s1*wg_s[n] + s2*wg_s[(n+1)&(Nn-1)];
            float p = powf(ws, gamma);
            wp[i] = p; lsum2 += p;
        }
        float inv2 = 1.f / (blockSum(lsum2, red) + EPSc);
#pragma unroll
        for (int i=0;i<8;i++){
            int n = tid + i*512;
            wout[b*Nn + n] = wp[i]*inv2;
        }
        __syncthreads();
    }
}

// ---------------- output ----------------
__global__ void k_out(const float* __restrict__ W_out, const float* __restrict__ b_out,
                      float* __restrict__ out)
{
    int wg = blockIdx.x*8 + (threadIdx.x>>5);
    int lane = threadIdx.x & 31;
    int b = wg >> 6, j = wg & 63;
    float acc = 0.f;
    for (int k = lane; k < Cc + Hh*Mm; k += 32){
        float s;
        if (k < Cc) s = g_h[b*Cc + k];
        else {
            int kk = k - Cc;
            s = g_reads[((kk>>6)*Bb + b)*Mm + (kk & 63)];
        }
        acc = fmaf(s, W_out[j*(Cc+Hh*Mm) + k], acc);
    }
#pragma unroll
    for (int o=16;o;o>>=1) acc += __shfl_xor_sync(0xffffffffu, acc, o);
    if (lane == 0) out[b*OUTd + j] = 1.f/(1.f + __expf(-(acc + b_out[j])));
}

// ---------------- launch ----------------
extern "C" void kernel_launch(void* const* d_in, const int* in_sizes, int n_in,
                              void* d_out, int out_size)
{
    // Resolve inputs BY ELEMENT COUNT (robust to any input ordering).
    const float *in_data=0, *memory=0, *h0=0, *c0=0, *prevW=0, *prevR=0;
    const float *W_ih=0, *b_ih=0, *W_hh=0, *b_hh=0, *W_out=0, *b_out=0;
    const float *W_addr=0, *b_addr=0, *W_ea=0, *b_ea=0;
    for (int i = 0; i < n_in; i++){
        const float* p = (const float*)d_in[i];
        switch (in_sizes[i]){
            case 16384:    in_data = p; break;
            case 67108864: memory  = p; break;
            case 131072:   if (!h0) h0 = p; else c0 = p; break;
            case 8388608:  prevW   = p; break;
            case 65536:    prevR   = p; break;
            case 655360:   W_ih    = p; break;
            case 2048:     if (!b_ih) b_ih = p; else b_hh = p; break;
            case 1048576:  W_hh    = p; break;
            case 49152:    W_out   = p; break;
            case 64:       b_out   = p; break;
            case 286720:   W_addr  = p; break;
            case 560:      b_addr  = p; break;
            case 262144:   W_ea    = p; break;
            case 512:      b_ea    = p; break;
            default: break;
        }
    }
    float* out = (float*)d_out;

    k_prep<<<(Bb*XK+255)/256, 256>>>(in_data, prevR);
    k_gates<<<dim3(4*Cc/8, Bb/8), 256>>>(h0, W_ih, b_ih, W_hh, b_hh);
    k_lstm<<<(Bb*Cc+255)/256, 256>>>(c0);
    k_addrea<<<dim3(134, Bb/8), 256>>>(W_addr, b_addr, W_ea, b_ea);
    k_params<<<256, 256>>>();

    dim3 pg(Nn/512, Bb);
    k_passA<<<pg, 256>>>(memory, 0, 1);
    k_wpair<<<Bb, 512>>>(0, 1, prevW);
    k_passB1<<<pg, 256>>>(memory, /*ea*/0, /*next keys*/2, 3, /*read*/0);
    k_wpair<<<Bb, 512>>>(2, 3, prevW);
    k_passBH<<<pg, 256>>>(1, 4, 5, 1);
    k_wpair<<<Bb, 512>>>(4, 5, prevW);
    k_passBH<<<pg, 256>>>(2, 6, 7, 2);
    k_wpair<<<Bb, 512>>>(6, 7, prevW);          // head 7's write is dead; w7 unused
    k_passC<<<pg, 256>>>(3);

    k_out<<<(Bb*OUTd)/8, 256>>>(W_out, b_out, out);
}